// round 2
// baseline (speedup 1.0000x reference)
#include <cuda_runtime.h>
#include <math.h>

// ---- problem constants (L=512 fixed by dataset; B,T derived from sizes) ----
#define LFIX   512
#define TILE   64
#define NT     8              // LFIX / TILE
#define NPAIR  36             // NT*(NT+1)/2
#define MAXB   16
#define MAXT   24
#define SP     65             // padded tile stride (bank-conflict free transpose)

#define SCONST 2.1972245773362196f   // log(9)

// scratch (static device memory: allowed; no allocations anywhere)
__device__ float g_ahat[(size_t)MAXB * LFIX * LFIX];   // 16.8 MB
__device__ float g_w   [(size_t)MAXB * LFIX * LFIX];   // 16.8 MB (upper tiles only used)
__device__ float g_rs  [(size_t)(MAXT + 1) * MAXB * LFIX]; // per-step rowsums

__device__ __forceinline__ float sigmoidf_(float v) { return 1.f / (1.f + __expf(-v)); }

// shared memory layout (floats)
//  sB  : TILE*SP      transpose-access tile
//  sN  : TILE*SP      staging (new a_hat of transposed tile)
//  sS  : TILE*SP      staging (a values, transposed)
//  sXI : 256, sXJ : 256   x rows for m recompute
//  sC  : 128          c_i (0..63), c_j (64..127)
//  sRow: 128          rowI / rowJ partials
#define SMEM_FLOATS (3 * TILE * SP + 256 + 256 + 128 + 128)

__device__ __forceinline__ void decode_pair(int p, int &ti, int &tj) {
    int t = 0;
    while (p >= NT - t) { p -= NT - t; t++; }
    ti = t; tj = t + p;
}

// ---------------- setup: u_mod, a_hat0, w, rowsum(a0) ----------------
__global__ void __launch_bounds__(256) setup_kernel(
    const float* __restrict__ uin, const float* __restrict__ xin, int B)
{
    extern __shared__ float sm[];
    float* sB  = sm;
    float* sN  = sm + TILE * SP;
    float* sS  = sm + 2 * TILE * SP;
    float* sXI = sm + 3 * TILE * SP;
    float* sXJ = sXI + 256;
    float* sC  = sXJ + 256;   (void)sC;
    float* sRow = sXJ + 256 + 128;

    const int job = blockIdx.x;
    const int b = job / NPAIR;
    int p = job % NPAIR;
    int ti, tj; decode_pair(p, ti, tj);
    const bool diag = (ti == tj);
    const int tid = threadIdx.x, tx = tid & 63, ty = tid >> 6;
    const int L = LFIX;
    const size_t mbase = (size_t)b * L * L;

    if (tid < 128) sRow[tid] = 0.f;
    {   // x rows (64 rows x 4 chans each side)
        int r = tid >> 2, c = tid & 3;
        sXI[tid] = xin[((size_t)b * L + ti * TILE + r) * 4 + c];
        sXJ[tid] = xin[((size_t)b * L + tj * TILE + r) * 4 + c];
    }
    {   // u tile (tj,ti) -> sB for transposed access
        const float* uB = uin + mbase + (size_t)(tj * TILE) * L + ti * TILE;
        #pragma unroll
        for (int r = 0; r < 16; r++) {
            int row = ty * 16 + r;
            sB[row * SP + tx] = uB[(size_t)row * L + tx];
        }
    }
    __syncthreads();

    const float* uA = uin + mbase + (size_t)(ti * TILE) * L + tj * TILE;
    float* rs0 = g_rs + (size_t)b * L;

    #pragma unroll 4
    for (int r = 0; r < 16; r++) {
        const int i = ty * 16 + r, j = tx;
        const int gi = ti * TILE + i, gj = tj * TILE + j;
        const size_t idxA = mbase + (size_t)gi * L + gj;

        float u1 = uA[(size_t)i * L + j];
        float u2 = sB[j * SP + i];
        float um1 = sigmoidf_(2.f * (u1 - SCONST)) * u1;
        float um2 = sigmoidf_(2.f * (u2 - SCONST)) * u2;
        float ah1 = sigmoidf_(um1) * sigmoidf_(2.f * (um1 - SCONST));
        float ah2 = sigmoidf_(um2) * sigmoidf_(2.f * (um2 - SCONST));
        float w = 0.5f * (um1 + um2);

        float m;
        int d = gi - gj; if (d < 0) d = -d;
        if (d <= 3) m = 0.f;
        else {
            float a1 = sXI[i*4+0], q1 = sXI[i*4+1], c1 = sXI[i*4+2], G1 = sXI[i*4+3];
            float a2 = sXJ[j*4+0], q2 = sXJ[j*4+1], c2 = sXJ[j*4+2], G2 = sXJ[j*4+3];
            m = a1*q2 + q1*a2 + c1*G2 + G1*c2 + q1*G2 + G1*q2;
        }
        float s = 0.5f * m * (ah1 * ah1 + ah2 * ah2);

        g_ahat[idxA] = ah1;
        g_w[idxA]    = w;
        if (!diag) { sN[j * SP + i] = ah2; sS[j * SP + i] = s; }

        float v = s;
        v += __shfl_down_sync(0xffffffff, v, 16);
        v += __shfl_down_sync(0xffffffff, v, 8);
        v += __shfl_down_sync(0xffffffff, v, 4);
        v += __shfl_down_sync(0xffffffff, v, 2);
        v += __shfl_down_sync(0xffffffff, v, 1);
        if ((tid & 31) == 0) atomicAdd(&sRow[i], v);
    }
    __syncthreads();

    if (!diag) {
        float* ahB = g_ahat + mbase + (size_t)(tj * TILE) * L + ti * TILE;
        #pragma unroll
        for (int r = 0; r < 16; r++) {
            int row = ty * 16 + r;
            ahB[(size_t)row * L + tx] = sN[row * SP + tx];
        }
        if (tid < 64) {
            float acc = 0.f;
            #pragma unroll 8
            for (int q = 0; q < 64; q++) acc += sS[tid * SP + q];
            sRow[64 + tid] = acc;
        }
        __syncthreads();
        if (tid < 64)       atomicAdd(&rs0[ti * TILE + tid], sRow[tid]);
        else if (tid < 128) atomicAdd(&rs0[tj * TILE + (tid - 64)], sRow[tid]);
    } else {
        if (tid < 64) atomicAdd(&rs0[ti * TILE + tid], sRow[tid]);
    }
}

// ---------------- one optimization step ----------------
__global__ void __launch_bounds__(256) step_kernel(
    float* __restrict__ out_t, const float* __restrict__ xin,
    int t, float alpha, float tau, int B)
{
    extern __shared__ float sm[];
    float* sB  = sm;
    float* sN  = sm + TILE * SP;
    float* sS  = sm + 2 * TILE * SP;
    float* sXI = sm + 3 * TILE * SP;
    float* sXJ = sXI + 256;
    float* sC  = sXJ + 256;
    float* sRow = sC + 128;

    const int job = blockIdx.x;
    const int b = job / NPAIR;
    int p = job % NPAIR;
    int ti, tj; decode_pair(p, ti, tj);
    const bool diag = (ti == tj);
    const int tid = threadIdx.x, tx = tid & 63, ty = tid >> 6;
    const int L = LFIX;
    const size_t mbase = (size_t)b * L * L;
    const int stride = B * L;

    if (tid < 128) sRow[tid] = 0.f;
    {
        int r = tid >> 2, c = tid & 3;
        sXI[tid] = xin[((size_t)b * L + ti * TILE + r) * 4 + c];
        sXJ[tid] = xin[((size_t)b * L + tj * TILE + r) * 4 + c];
    }
    if (tid < 128) {
        // reconstruct lambda_t and c_t for this block's 128 rows from rs history
        const int row = (tid < 64) ? (ti * TILE + tid) : (tj * TILE + (tid - 64));
        const float* rs = g_rs + (size_t)b * L + row;
        float lm = fmaxf(rs[0] - 1.f, 0.f);
        float bk = 0.1f;
        for (int k = 1; k <= t; k++) {
            lm += bk * fmaxf(rs[(size_t)k * stride] - 1.f, 0.f);
            bk *= 0.99f;
        }
        float rst = rs[(size_t)t * stride];
        sC[tid] = lm * sigmoidf_(2.f * (rst - 1.f));
    }
    {   // a_hat tile (tj,ti) -> sB
        const float* src = g_ahat + mbase + (size_t)(tj * TILE) * L + ti * TILE;
        #pragma unroll
        for (int r = 0; r < 16; r++) {
            int row = ty * 16 + r;
            sB[row * SP + tx] = src[(size_t)row * L + tx];
        }
    }
    __syncthreads();

    float* rsn = g_rs + (size_t)(t + 1) * stride + (size_t)b * L;

    #pragma unroll 4
    for (int r = 0; r < 16; r++) {
        const int i = ty * 16 + r, j = tx;
        const int gi = ti * TILE + i, gj = tj * TILE + j;
        const size_t idxA = mbase + (size_t)gi * L + gj;

        float ah1 = g_ahat[idxA];
        float w   = g_w[idxA];
        float ah2 = sB[j * SP + i];

        float m;
        int d = gi - gj; if (d < 0) d = -d;
        if (d <= 3) m = 0.f;
        else {
            float a1 = sXI[i*4+0], q1 = sXI[i*4+1], c1 = sXI[i*4+2], G1 = sXI[i*4+3];
            float a2 = sXJ[j*4+0], q2 = sXJ[j*4+1], c2 = sXJ[j*4+2], G2 = sXJ[j*4+3];
            m = a1*q2 + q1*a2 + c1*G2 + G1*c2 + q1*G2 + G1*q2;
        }
        float gsum = sC[i] + sC[64 + j] - w;   // -(u_ij+u_ji)/2 + c_i + c_j
        float coef = alpha * m * gsum;

        float nh1 = ah1 - coef * ah1;
        nh1 = fminf(fmaxf(fabsf(nh1) - tau, 0.f), 1.f);
        float nh2 = ah2 - coef * ah2;
        nh2 = fminf(fmaxf(fabsf(nh2) - tau, 0.f), 1.f);
        float s = 0.5f * m * (nh1 * nh1 + nh2 * nh2);

        g_ahat[idxA] = nh1;
        __stcs(&out_t[idxA], s);               // streaming store: don't pollute L2
        if (!diag) { sN[j * SP + i] = nh2; sS[j * SP + i] = s; }

        float v = s;                            // warp covers one row i
        v += __shfl_down_sync(0xffffffff, v, 16);
        v += __shfl_down_sync(0xffffffff, v, 8);
        v += __shfl_down_sync(0xffffffff, v, 4);
        v += __shfl_down_sync(0xffffffff, v, 2);
        v += __shfl_down_sync(0xffffffff, v, 1);
        if ((tid & 31) == 0) atomicAdd(&sRow[i], v);
    }
    __syncthreads();

    if (!diag) {
        float* ahB  = g_ahat + mbase + (size_t)(tj * TILE) * L + ti * TILE;
        float* outB = out_t  + mbase + (size_t)(tj * TILE) * L + ti * TILE;
        #pragma unroll
        for (int r = 0; r < 16; r++) {
            int row = ty * 16 + r;
            ahB[(size_t)row * L + tx] = sN[row * SP + tx];
            __stcs(&outB[(size_t)row * L + tx], sS[row * SP + tx]);
        }
        if (tid < 64) {
            float acc = 0.f;
            #pragma unroll 8
            for (int q = 0; q < 64; q++) acc += sS[tid * SP + q];
            sRow[64 + tid] = acc;
        }
        __syncthreads();
        if (tid < 64)       atomicAdd(&rsn[ti * TILE + tid], sRow[tid]);
        else if (tid < 128) atomicAdd(&rsn[tj * TILE + (tid - 64)], sRow[tid]);
    } else {
        if (tid < 64) atomicAdd(&rsn[ti * TILE + tid], sRow[tid]);
    }
}

// ---------------- host ----------------
extern "C" void kernel_launch(void* const* d_in, const int* in_sizes, int n_in,
                              void* d_out, int out_size)
{
    // identify inputs by size (robust to ordering): u = largest, x = next largest
    int iu = 0;
    for (int i = 1; i < n_in; i++) if (in_sizes[i] > in_sizes[iu]) iu = i;
    int ix = -1;
    for (int i = 0; i < n_in; i++) {
        if (i == iu) continue;
        if (ix < 0 || in_sizes[i] > in_sizes[ix]) ix = i;
    }
    const float* u = (const float*)d_in[iu];
    const float* x = (const float*)d_in[ix];
    const long long usz = in_sizes[iu];
    const long long xsz = in_sizes[ix];
    const int L = (int)(4LL * usz / xsz);      // 512
    const int B = (int)(xsz / (4LL * L));      // 16
    const int T = (int)((long long)out_size / usz); // 20
    float* out = (float*)d_out;

    void* rs_ptr = nullptr;
    cudaGetSymbolAddress(&rs_ptr, g_rs);
    cudaMemsetAsync(rs_ptr, 0, sizeof(float) * (size_t)(T + 1) * B * L);

    const int smem_bytes = SMEM_FLOATS * sizeof(float);
    cudaFuncSetAttribute(setup_kernel, cudaFuncAttributeMaxDynamicSharedMemorySize, smem_bytes);
    cudaFuncSetAttribute(step_kernel,  cudaFuncAttributeMaxDynamicSharedMemorySize, smem_bytes);

    dim3 grid(B * NPAIR), blk(256);
    setup_kernel<<<grid, blk, smem_bytes>>>(u, x, B);

    double alpha = 0.01;
    for (int t = 0; t < T; t++) {
        float a   = (float)alpha;
        float tau = (float)(alpha * 0.99);     // RHO * alpha * DECAY
        step_kernel<<<grid, blk, smem_bytes>>>(out + (size_t)t * usz, x, t, a, tau, B);
        alpha *= 0.99;
    }
}

// round 5
// speedup vs baseline: 1.8416x; 1.8416x over previous
#include <cuda_runtime.h>

// ---- problem constants (L=512 fixed by dataset; B,T derived from sizes) ----
#define LFIX   512
#define TILE   64
#define NT     8              // LFIX / TILE
#define NPAIR  36             // NT*(NT+1)/2
#define MAXB   16
#define MAXT   32
#define SP     65             // padded stride for transpose-access staging

#define SCONST 2.1972245773362196f   // log(9)

__device__ float g_rs [(size_t)(MAXT + 1) * MAXB * LFIX]; // per-step rowsums
__device__ int   g_bar[MAXB];                             // per-batch barrier counters

__device__ __forceinline__ float sigmoidf_(float v) { return 1.f / (1.f + __expf(-v)); }

// smem layout (floats): sW[4096] sM[4096] sS[64*65] sXI[256] sXJ[256] sC[128] sRow[128]
#define SMEM_FLOATS (4096 + 4096 + 64 * SP + 256 + 256 + 128 + 128)

__device__ __forceinline__ void decode_pair(int p, int &ti, int &tj) {
    int t = 0;
    while (p >= NT - t) { p -= NT - t; t++; }
    ti = t; tj = t + p;
}

// per-batch spin barrier (monotonic counter; reset by host memset each launch)
__device__ __forceinline__ void batch_barrier(int b, int target) {
    __syncthreads();
    if (threadIdx.x == 0) {
        __threadfence();
        atomicAdd(&g_bar[b], 1);
        volatile int* c = g_bar + b;
        while (*c < target) __nanosleep(64);
        __threadfence();
    }
    __syncthreads();
}

__global__ void __launch_bounds__(256, 4) persist_kernel(
    float* __restrict__ out, const float* __restrict__ uin,
    const float* __restrict__ xin, int B, int T)
{
    extern __shared__ float sm[];
    float* sW   = sm;                 // w tile (symmetric)
    float* sM   = sW + 4096;          // m tile (symmetric)
    float* sS   = sM + 4096;          // staging: init u-transpose, then per-step s-transpose
    float* sXI  = sS + 64 * SP;
    float* sXJ  = sXI + 256;
    float* sC   = sXJ + 256;          // c_i (0..63), c_j (64..127)
    float* sRow = sC + 128;           // rowsum partials

    const int job = blockIdx.x;
    const int b = job / NPAIR;
    int p = job % NPAIR;
    int ti, tj; decode_pair(p, ti, tj);
    const bool diag = (ti == tj);
    const int tid = threadIdx.x;
    const int j = tid & 63, ty = tid >> 6;
    const int L = LFIX;
    const size_t usz   = (size_t)B * L * L;
    const size_t mbase = (size_t)b * L * L;
    const int stride = B * L;

    const float* uA = uin + mbase + (size_t)(ti * TILE) * L + tj * TILE;
    const float* uB = uin + mbase + (size_t)(tj * TILE) * L + ti * TILE;

    // ---------------- init: x, u staging ----------------
    {
        int r0 = tid >> 2, c0 = tid & 3;
        sXI[tid] = xin[((size_t)(b * L + ti * TILE + r0)) * 4 + c0];
        sXJ[tid] = xin[((size_t)(b * L + tj * TILE + r0)) * 4 + c0];
    }
    if (tid < 128) sRow[tid] = 0.f;
    #pragma unroll
    for (int r = 0; r < 16; r++) {
        int row = ty * 16 + r;
        sS[row * SP + j] = uB[(size_t)row * L + j];
    }
    __syncthreads();

    float ah1[16], ah2[16];   // a_hat(i,j) and a_hat(j,i), persistent in registers
    float lam = 0.f;          // lambda for this thread's row (tid<128)

    // ---------------- init: u_mod, a_hat0, w, m, rowsum(a0) ----------------
    {
        float csum = 0.f;
        #pragma unroll
        for (int r = 0; r < 16; r++) {
            const int i = ty * 16 + r;
            const int gi = ti * TILE + i, gj = tj * TILE + j;
            float u1 = uA[(size_t)i * L + j];
            float u2 = sS[j * SP + i];
            float um1 = sigmoidf_(2.f * (u1 - SCONST)) * u1;
            float um2 = sigmoidf_(2.f * (u2 - SCONST)) * u2;
            float a1 = sigmoidf_(um1) * sigmoidf_(2.f * (um1 - SCONST));
            float a2 = sigmoidf_(um2) * sigmoidf_(2.f * (um2 - SCONST));
            ah1[r] = a1; ah2[r] = a2;
            sW[i * 64 + j] = 0.5f * (um1 + um2);

            float m;
            int d = gi - gj; if (d < 0) d = -d;
            if (d <= 3) m = 0.f;
            else {
                float A1 = sXI[i*4+0], U1 = sXI[i*4+1], C1 = sXI[i*4+2], G1 = sXI[i*4+3];
                float A2 = sXJ[j*4+0], U2 = sXJ[j*4+1], C2 = sXJ[j*4+2], G2 = sXJ[j*4+3];
                m = A1*U2 + U1*A2 + C1*G2 + G1*C2 + U1*G2 + G1*U2;
            }
            sM[i * 64 + j] = m;

            float s = 0.5f * m * (a1 * a1 + a2 * a2);
            float v = s;
            v += __shfl_down_sync(0xffffffffu, v, 16);
            v += __shfl_down_sync(0xffffffffu, v, 8);
            v += __shfl_down_sync(0xffffffffu, v, 4);
            v += __shfl_down_sync(0xffffffffu, v, 2);
            v += __shfl_down_sync(0xffffffffu, v, 1);
            if ((tid & 31) == 0) atomicAdd(&sRow[i], v);
            if (!diag) csum += s;
        }
        if (!diag) atomicAdd(&sRow[64 + j], csum);
    }
    __syncthreads();
    {
        float* rs0 = g_rs + (size_t)b * L;
        if (tid < 64)                    atomicAdd(&rs0[ti * TILE + tid], sRow[tid]);
        else if (tid < 128 && !diag)     atomicAdd(&rs0[tj * TILE + (tid - 64)], sRow[tid]);
    }

    int bcount = 1;
    batch_barrier(b, NPAIR * bcount); bcount++;

    // ---------------- T optimization steps ----------------
    float alpha = 0.01f, beta_run = 0.1f;
    for (int t = 0; t < T; t++) {
        const float tau = alpha * 0.99f;   // RHO * alpha * DECAY

        if (tid < 128) {
            int row = (tid < 64) ? (ti * TILE + tid) : (tj * TILE + (tid - 64));
            float rst = __ldcg(&g_rs[(size_t)t * stride + (size_t)b * L + row]);
            float rl = fmaxf(rst - 1.f, 0.f);
            if (t == 0) lam = rl;
            else        lam += beta_run * rl;
            sC[tid]  = lam * sigmoidf_(2.f * (rst - 1.f));
            sRow[tid] = 0.f;
        }
        __syncthreads();

        float* outA = out + (size_t)t * usz + mbase + (size_t)(ti * TILE) * L + tj * TILE;
        float csum = 0.f;
        #pragma unroll
        for (int r = 0; r < 16; r++) {
            const int i = ty * 16 + r;
            float w = sW[i * 64 + j];
            float m = sM[i * 64 + j];
            float coef = alpha * m * (sC[i] + sC[64 + j] - w);
            float f = 1.f - coef;
            float n1 = fminf(fmaxf(fabsf(ah1[r] * f) - tau, 0.f), 1.f);
            float n2 = fminf(fmaxf(fabsf(ah2[r] * f) - tau, 0.f), 1.f);
            ah1[r] = n1; ah2[r] = n2;
            float s = 0.5f * m * (n1 * n1 + n2 * n2);   // a(i,j) == a(j,i)

            __stcs(&outA[(size_t)i * L + j], s);
            if (!diag) sS[j * SP + i] = s;

            float v = s;
            v += __shfl_down_sync(0xffffffffu, v, 16);
            v += __shfl_down_sync(0xffffffffu, v, 8);
            v += __shfl_down_sync(0xffffffffu, v, 4);
            v += __shfl_down_sync(0xffffffffu, v, 2);
            v += __shfl_down_sync(0xffffffffu, v, 1);
            if ((tid & 31) == 0) atomicAdd(&sRow[i], v);
            if (!diag) csum += s;
        }
        if (!diag) atomicAdd(&sRow[64 + j], csum);
        __syncthreads();

        if (!diag) {   // coalesced write of the transposed tile
            float* outB = out + (size_t)t * usz + mbase + (size_t)(tj * TILE) * L + ti * TILE;
            #pragma unroll
            for (int r = 0; r < 16; r++) {
                int row = ty * 16 + r;
                __stcs(&outB[(size_t)row * L + j], sS[row * SP + j]);
            }
        }

        if (t + 1 < T) {
            float* rsn = g_rs + (size_t)(t + 1) * stride + (size_t)b * L;
            if (tid < 64)                atomicAdd(&rsn[ti * TILE + tid], sRow[tid]);
            else if (tid < 128 && !diag) atomicAdd(&rsn[tj * TILE + (tid - 64)], sRow[tid]);
            batch_barrier(b, NPAIR * bcount); bcount++;
        }

        if (t > 0) beta_run *= 0.99f;
        alpha *= 0.99f;
    }
}

// ---------------- host ----------------
extern "C" void kernel_launch(void* const* d_in, const int* in_sizes, int n_in,
                              void* d_out, int out_size)
{
    // identify inputs by size: u = largest, x = next largest
    int iu = 0;
    for (int i = 1; i < n_in; i++) if (in_sizes[i] > in_sizes[iu]) iu = i;
    int ix = -1;
    for (int i = 0; i < n_in; i++) {
        if (i == iu) continue;
        if (ix < 0 || in_sizes[i] > in_sizes[ix]) ix = i;
    }
    const float* u = (const float*)d_in[iu];
    const float* x = (const float*)d_in[ix];
    const long long usz = in_sizes[iu];
    const long long xsz = in_sizes[ix];
    const int L = (int)(4LL * usz / xsz);           // 512
    const int B = (int)(xsz / (4LL * L));           // 16
    const int T = (int)((long long)out_size / usz); // 20
    float* out = (float*)d_out;

    void* rs_ptr = nullptr; cudaGetSymbolAddress(&rs_ptr, g_rs);
    void* bar_ptr = nullptr; cudaGetSymbolAddress(&bar_ptr, g_bar);
    cudaMemsetAsync(rs_ptr, 0, sizeof(float) * (size_t)(T + 1) * B * L);
    cudaMemsetAsync(bar_ptr, 0, sizeof(int) * MAXB);

    const int smem_bytes = SMEM_FLOATS * sizeof(float);
    cudaFuncSetAttribute(persist_kernel, cudaFuncAttributeMaxDynamicSharedMemorySize, smem_bytes);

    persist_kernel<<<B * NPAIR, 256, smem_bytes>>>(out, u, x, B, T);
}

// round 6
// speedup vs baseline: 2.2330x; 1.2126x over previous
#include <cuda_runtime.h>

// ---- problem constants (L=512 fixed; B,T derived from sizes) ----
#define LFIX   512
#define TILE   64
#define NT     8
#define NPAIR  36            // NT*(NT+1)/2
#define MAXB   16
#define MAXT   32
#define SCONST 2.1972245773362196f   // log(9)

__device__ float g_rs [(size_t)(MAXT + 1) * MAXB * LFIX]; // per-step rowsums
__device__ int   g_bar[MAXB];                             // per-batch barrier counters

__device__ __forceinline__ float sigmoidf_(float v) { return 1.f / (1.f + __expf(-v)); }

// smem (floats): sW 4096 | sM 4096 | sA 4096 | sPC 1024 | sC 128
#define SMEM_FLOATS (4096 * 3 + 1024 + 128)

__device__ __forceinline__ void decode_pair(int p, int &ti, int &tj) {
    int t = 0;
    while (p >= NT - t) { p -= NT - t; t++; }
    ti = t; tj = t + p;
}

// per-batch spin barrier (monotonic counter; host-zeroed each launch)
__device__ __forceinline__ void batch_barrier(int b, int target) {
    __threadfence();            // make this thread's global REDs visible
    __syncthreads();
    if (threadIdx.x == 0) {
        atomicAdd(&g_bar[b], 1);
        volatile int* c = g_bar + b;
        while (*c < target) __nanosleep(32);
        __threadfence();
    }
    __syncthreads();
}

__global__ void __launch_bounds__(256, 4) persist_kernel(
    float* __restrict__ out, const float* __restrict__ uin,
    const float* __restrict__ xin, int B, int T)
{
    extern __shared__ float sm[];
    float* sW  = sm;              // w tile, i-major swizzled
    float* sM  = sW + 4096;       // m tile, i-major swizzled
    float* sA  = sM + 4096;       // s staging, i-major swizzled
    float* sPC = sA + 4096;       // col-sum partials [tyy][j] (16 x 64)
    float* sC  = sPC + 1024;      // c_i (0..63), c_j (64..127)

    const int job = blockIdx.x;
    const int b = job / NPAIR;
    int p = job % NPAIR;
    int ti, tj; decode_pair(p, ti, tj);
    const bool diag = (ti == tj);
    const int tid = threadIdx.x;
    const int tx = tid & 15, tyy = tid >> 4;
    const int i0 = 4 * tyy, j0 = 4 * tx;
    const int L = LFIX;
    const size_t usz   = (size_t)B * L * L;
    const size_t mbase = (size_t)b * L * L;
    const int stride = B * L;
    const int swzg = 4 * (tx ^ (tyy & 7));      // swizzled group offset for this thread's stage writes

    const float* uA = uin + mbase + (size_t)(ti * TILE) * L + tj * TILE;
    const float* uB = uin + mbase + (size_t)(tj * TILE) * L + ti * TILE;

    float ah1[16], ah2[16];   // a_hat(i,j) / a_hat(j,i), persistent in registers
    float lam = 0.f;

    // ================= init: u_mod, a_hat0, w, m, s0 =================
    {
        float4 u2v[4], xj[4];
        #pragma unroll
        for (int jj = 0; jj < 4; jj++) {
            u2v[jj] = *(const float4*)&uB[(size_t)(j0 + jj) * L + i0];
            xj[jj]  = *(const float4*)&xin[(size_t)(b * L + tj * TILE + j0 + jj) * 4];
        }
        float cs4[4] = {0.f, 0.f, 0.f, 0.f};
        #pragma unroll
        for (int ii = 0; ii < 4; ii++) {
            const int i = i0 + ii, gi = ti * TILE + i;
            float4 u1v = *(const float4*)&uA[(size_t)i * L + j0];
            float4 xi  = *(const float4*)&xin[(size_t)(b * L + ti * TILE + i) * 4];
            float w4[4], m4[4], s4[4];
            #pragma unroll
            for (int jj = 0; jj < 4; jj++) {
                const int gj = tj * TILE + j0 + jj;
                float u1 = ((const float*)&u1v)[jj];
                float u2 = ((const float*)&u2v[jj])[ii];
                float um1 = sigmoidf_(2.f * (u1 - SCONST)) * u1;
                float um2 = sigmoidf_(2.f * (u2 - SCONST)) * u2;
                float a1 = sigmoidf_(um1) * sigmoidf_(2.f * (um1 - SCONST));
                float a2 = sigmoidf_(um2) * sigmoidf_(2.f * (um2 - SCONST));
                ah1[ii * 4 + jj] = a1;
                ah2[ii * 4 + jj] = a2;
                w4[jj] = 0.5f * (um1 + um2);
                int d = gi - gj; if (d < 0) d = -d;
                float m = 0.f;
                if (d > 3) {
                    float A2 = ((const float*)&xj[jj])[0], U2 = ((const float*)&xj[jj])[1];
                    float C2 = ((const float*)&xj[jj])[2], G2 = ((const float*)&xj[jj])[3];
                    m = xi.x * U2 + xi.y * A2 + xi.z * G2 + xi.w * C2 + xi.y * G2 + xi.w * U2;
                }
                m4[jj] = m;
                float s = 0.5f * m * (a1 * a1 + a2 * a2);
                s4[jj] = s;
                cs4[jj] += s;
            }
            *(float4*)&sW[i * 64 + swzg] = make_float4(w4[0], w4[1], w4[2], w4[3]);
            *(float4*)&sM[i * 64 + swzg] = make_float4(m4[0], m4[1], m4[2], m4[3]);
            *(float4*)&sA[i * 64 + swzg] = make_float4(s4[0], s4[1], s4[2], s4[3]);
        }
        if (!diag)
            *(float4*)&sPC[tyy * 64 + j0] = make_float4(cs4[0], cs4[1], cs4[2], cs4[3]);
        __syncthreads();

        // reductions -> g_rs[0]
        float* rs0 = g_rs + (size_t)b * L;
        if (tid < 64) {
            float4 acc = make_float4(0.f, 0.f, 0.f, 0.f);
            #pragma unroll
            for (int g = 0; g < 16; g++) {
                int gg = (g + tid) & 15;
                float4 v = *(const float4*)&sA[tid * 64 + 4 * gg];
                acc.x += v.x; acc.y += v.y; acc.z += v.z; acc.w += v.w;
            }
            atomicAdd(&rs0[ti * TILE + tid], acc.x + acc.y + acc.z + acc.w);
        } else if (tid < 128 && !diag) {
            int j = tid - 64;
            float a0 = 0.f, a1_ = 0.f, a2_ = 0.f, a3_ = 0.f;
            #pragma unroll
            for (int q = 0; q < 16; q += 4) {
                a0 += sPC[(q + 0) * 64 + j];
                a1_ += sPC[(q + 1) * 64 + j];
                a2_ += sPC[(q + 2) * 64 + j];
                a3_ += sPC[(q + 3) * 64 + j];
            }
            atomicAdd(&rs0[tj * TILE + j], a0 + a1_ + a2_ + a3_);
        }
    }

    int bcount = 1;
    batch_barrier(b, NPAIR * bcount); bcount++;

    // ================= T optimization steps =================
    float alpha = 0.01f, beta_run = 0.1f;
    for (int t = 0; t < T; t++) {
        const float tau = alpha * 0.99f;    // RHO * alpha * DECAY

        if (tid < 128) {
            int row = (tid < 64) ? (ti * TILE + tid) : (tj * TILE + (tid - 64));
            float rst = __ldcg(&g_rs[(size_t)t * stride + (size_t)b * L + row]);
            float rl = fmaxf(rst - 1.f, 0.f);
            lam = (t == 0) ? rl : (lam + beta_run * rl);
            sC[tid] = lam * sigmoidf_(2.f * (rst - 1.f));
        }
        __syncthreads();

        float4 ci4 = *(const float4*)&sC[i0];
        float4 cj4 = *(const float4*)&sC[64 + j0];
        float cs4[4] = {0.f, 0.f, 0.f, 0.f};
        float* outT = out + (size_t)t * usz + mbase;

        #pragma unroll
        for (int ii = 0; ii < 4; ii++) {
            const int i = i0 + ii;
            float4 w4 = *(const float4*)&sW[i * 64 + swzg];
            float4 m4 = *(const float4*)&sM[i * 64 + swzg];
            const float ci = ((const float*)&ci4)[ii];
            float s4[4];
            #pragma unroll
            for (int jj = 0; jj < 4; jj++) {
                float m = ((const float*)&m4)[jj];
                float w = ((const float*)&w4)[jj];
                float coef = alpha * m * (ci + ((const float*)&cj4)[jj] - w);
                float f = 1.f - coef;
                float n1 = fminf(fmaxf(fabsf(ah1[ii * 4 + jj] * f) - tau, 0.f), 1.f);
                float n2 = fminf(fmaxf(fabsf(ah2[ii * 4 + jj] * f) - tau, 0.f), 1.f);
                ah1[ii * 4 + jj] = n1;
                ah2[ii * 4 + jj] = n2;
                float s = 0.5f * m * (n1 * n1 + n2 * n2);
                s4[jj] = s;
                cs4[jj] += s;
            }
            float4 sv = make_float4(s4[0], s4[1], s4[2], s4[3]);
            *(float4*)&sA[i * 64 + swzg] = sv;
            __stcs((float4*)&outT[(size_t)(ti * TILE + i) * L + tj * TILE + j0], sv);
        }
        if (!diag)
            *(float4*)&sPC[tyy * 64 + j0] = make_float4(cs4[0], cs4[1], cs4[2], cs4[3]);
        __syncthreads();

        // reductions -> g_rs[t+1] (skip after last step)
        if (t + 1 < T) {
            float* rsn = g_rs + (size_t)(t + 1) * stride + (size_t)b * L;
            if (tid < 64) {
                float4 acc = make_float4(0.f, 0.f, 0.f, 0.f);
                #pragma unroll
                for (int g = 0; g < 16; g++) {
                    int gg = (g + tid) & 15;
                    float4 v = *(const float4*)&sA[tid * 64 + 4 * gg];
                    acc.x += v.x; acc.y += v.y; acc.z += v.z; acc.w += v.w;
                }
                atomicAdd(&rsn[ti * TILE + tid], acc.x + acc.y + acc.z + acc.w);
            } else if (tid < 128 && !diag) {
                int j = tid - 64;
                float a0 = 0.f, a1_ = 0.f, a2_ = 0.f, a3_ = 0.f;
                #pragma unroll
                for (int q = 0; q < 16; q += 4) {
                    a0 += sPC[(q + 0) * 64 + j];
                    a1_ += sPC[(q + 1) * 64 + j];
                    a2_ += sPC[(q + 2) * 64 + j];
                    a3_ += sPC[(q + 3) * 64 + j];
                }
                atomicAdd(&rsn[tj * TILE + j], a0 + a1_ + a2_ + a3_);
            }
        }

        // B (transposed) tile store: rows j' = 4*tyy+jj, cols 4*tx..+3
        if (!diag) {
            #pragma unroll
            for (int jj = 0; jj < 4; jj++) {
                const int j = 4 * tyy + jj;
                const int goff = 4 * (tyy ^ (tx & 7)) + jj;   // 4*((j>>2)^(tx&7)) + (j&3)
                float4 v;
                v.x = sA[(4 * tx + 0) * 64 + goff];
                v.y = sA[(4 * tx + 1) * 64 + goff];
                v.z = sA[(4 * tx + 2) * 64 + goff];
                v.w = sA[(4 * tx + 3) * 64 + goff];
                __stcs((float4*)&outT[(size_t)(tj * TILE + j) * L + ti * TILE + 4 * tx], v);
            }
        }

        if (t + 1 < T) { batch_barrier(b, NPAIR * bcount); bcount++; }

        if (t > 0) beta_run *= 0.99f;
        alpha *= 0.99f;
    }
}

// ---------------- host ----------------
extern "C" void kernel_launch(void* const* d_in, const int* in_sizes, int n_in,
                              void* d_out, int out_size)
{
    // identify inputs by size: u = largest, x = next largest
    int iu = 0;
    for (int i = 1; i < n_in; i++) if (in_sizes[i] > in_sizes[iu]) iu = i;
    int ix = -1;
    for (int i = 0; i < n_in; i++) {
        if (i == iu) continue;
        if (ix < 0 || in_sizes[i] > in_sizes[ix]) ix = i;
    }
    const float* u = (const float*)d_in[iu];
    const float* x = (const float*)d_in[ix];
    const long long usz = in_sizes[iu];
    const long long xsz = in_sizes[ix];
    const int L = (int)(4LL * usz / xsz);           // 512
    const int B = (int)(xsz / (4LL * L));           // 16
    const int T = (int)((long long)out_size / usz); // 20
    float* out = (float*)d_out;

    void* rs_ptr = nullptr;  cudaGetSymbolAddress(&rs_ptr, g_rs);
    void* bar_ptr = nullptr; cudaGetSymbolAddress(&bar_ptr, g_bar);
    cudaMemsetAsync(rs_ptr, 0, sizeof(float) * (size_t)(T + 1) * B * L);
    cudaMemsetAsync(bar_ptr, 0, sizeof(int) * MAXB);

    const int smem_bytes = SMEM_FLOATS * sizeof(float);
    cudaFuncSetAttribute(persist_kernel, cudaFuncAttributeMaxDynamicSharedMemorySize, smem_bytes);

    persist_kernel<<<B * NPAIR, 256, smem_bytes>>>(out, u, x, B, T);
}